// round 13
// baseline (speedup 1.0000x reference)
#include <cuda_runtime.h>
#include <cstdint>

#define NN 16384
#define MM 8192
#define EE 524288
#define DD 128

// ========= GEMM1 (mma.sync tf32, packed-B, BM=64, BK=64, 2-stage, occ2) ====
#define BM1 64
#define BK1 64
#define NK1 (MM/BK1)                 // 128 K-stages
#define A1_PITCH 68                  // A smem pitch (floats): conflict-free frags
#define A1_FLOATS (BM1*A1_PITCH)     // 4352
#define B1_FLOATS 8192               // packed B per 64-K stage (2 x 4096)
#define STG1_FLOATS (A1_FLOATS + B1_FLOATS)   // 12544
#define GEMM1_SMEM (2*STG1_FLOATS*4)          // 100352 B -> 2 CTAs/SM
#define PB_F2 ((size_t)(MM/32)*2048)          // 524288 float2 total

// ================= GEMM2 (mma.sync) tiling =================
#define BM 128
#define BN 128
#define BK 32
#define AST 36
#define BST 132
#define SMEM_FLOATS (2*BM*AST + 2*BK*BST)
#define SMEM_BYTES  (SMEM_FLOATS*4)
#define EPI_PITCH 133

// ---------------- device scratch (static, no allocation) ----------------
__device__ int   g_out_cnt[NN];
__device__ int   g_in_cnt[NN];
__device__ int   g_cursor[NN];
__device__ int   g_row_ptr[NN+1];
__device__ int   g_csr[EE];
__device__ float g_rs_out[NN];
__device__ float g_rs_in[NN];
__device__ float g_xf[NN*DD];          // inc @ nh  (UNscaled; rs_out applied in spmm)
__device__ float g_agg[NN*2*DD];       // [aggc | aggf]
__device__ float g_pb[(size_t)(MM/32)*4096];   // next_h fragment-packed, rna (4MB)
__device__ float g_wcat[2*DD*DD];
__device__ float g_b2[DD];

// ---------------- helpers ----------------
__device__ __forceinline__ uint32_t f2tf(float x){
    uint32_t r; asm("cvt.rna.tf32.f32 %0, %1;" : "=r"(r) : "f"(x)); return r;
}
__device__ __forceinline__ float rnaf(float x){ return __uint_as_float(f2tf(x)); }
__device__ __forceinline__ void cp16(float* s, const float* g){
    unsigned sa = (unsigned)__cvta_generic_to_shared(s);
    asm volatile("cp.async.cg.shared.global [%0], [%1], 16;\n" :: "r"(sa), "l"(g));
}
__device__ __forceinline__ void mma8(float* c, const uint32_t* a, uint32_t b0, uint32_t b1){
    asm volatile("mma.sync.aligned.m16n8k8.row.col.f32.tf32.tf32.f32 "
        "{%0,%1,%2,%3},{%4,%5,%6,%7},{%8,%9},{%0,%1,%2,%3};\n"
        : "+f"(c[0]),"+f"(c[1]),"+f"(c[2]),"+f"(c[3])
        : "r"(a[0]),"r"(a[1]),"r"(a[2]),"r"(a[3]),"r"(b0),"r"(b1));
}

// ---------------- small kernels ----------------
__global__ void zero_kernel(){
    int i = blockIdx.x*blockDim.x + threadIdx.x;
    if (i < NN){ g_out_cnt[i]=0; g_in_cnt[i]=0; g_cursor[i]=0; }
}

__global__ void degree_kernel(const int* __restrict__ src, const int* __restrict__ dst){
    int e = blockIdx.x*blockDim.x + threadIdx.x;
    if (e < EE){ atomicAdd(&g_out_cnt[src[e]],1); atomicAdd(&g_in_cnt[dst[e]],1); }
}

__global__ void scan_kernel(){
    __shared__ int ssum[1024];
    int tid = threadIdx.x;
    int loc[16]; int sum = 0;
    #pragma unroll
    for (int j=0;j<16;j++){ loc[j] = g_in_cnt[tid*16+j]; sum += loc[j]; }
    ssum[tid] = sum; __syncthreads();
    for (int off=1; off<1024; off<<=1){
        int v = (tid >= off) ? ssum[tid-off] : 0;
        __syncthreads();
        ssum[tid] += v;
        __syncthreads();
    }
    int run = ssum[tid] - sum;
    #pragma unroll
    for (int j=0;j<16;j++){ g_row_ptr[tid*16+j] = run; run += loc[j]; }
    if (tid == 1023) g_row_ptr[NN] = run;
    for (int i=tid; i<NN; i+=1024){
        g_rs_in[i]  = rsqrtf((float)g_in_cnt[i]  + 1.f);
        g_rs_out[i] = rsqrtf((float)g_out_cnt[i] + 1.f);
    }
}

__global__ void scatter_kernel(const int* __restrict__ src, const int* __restrict__ dst){
    int e = blockIdx.x*blockDim.x + threadIdx.x;
    if (e < EE){
        int d = dst[e];
        int p = g_row_ptr[d] + atomicAdd(&g_cursor[d], 1);
        g_csr[p] = src[e];
    }
}

// Pack next_h [K=8192, N=128] into mma-fragment order, tf32-rna.
__global__ void pack_b_kernel(const float* __restrict__ nh){
    size_t idx = (size_t)blockIdx.x*blockDim.x + threadIdx.x;
    if (idx >= PB_F2) return;
    int lane = (int)(idx & 31);
    int ct   = (int)((idx >> 5) & 15);
    int kk4  = (int)((idx >> 9) & 3);
    int kt   = (int)(idx >> 11);
    int k0 = kt*32 + kk4*8 + (lane & 3);
    int n  = ct*8 + (lane >> 2);
    float2 v;
    v.x = rnaf(nh[(size_t)k0*DD + n]);
    v.y = rnaf(nh[(size_t)(k0+4)*DD + n]);
    ((float2*)g_pb)[idx] = v;
}

__global__ void prep_kernel(const float* __restrict__ Wc, const float* __restrict__ bc,
                            const float* __restrict__ Wf, const float* __restrict__ bf,
                            const float* __restrict__ cw, const float* __restrict__ tw){
    int i = blockIdx.x*blockDim.x + threadIdx.x;
    if (i < 2*DD*DD){
        int k = i >> 7, j = i & 127;
        float w = (k < DD) ? Wc[k*DD+j]*cw[j] : Wf[(k-DD)*DD+j]*tw[j];
        g_wcat[i] = __uint_as_float(f2tf(0.5f*w));
        if (i < DD) g_b2[i] = 0.5f*(bc[i]*cw[i] + bf[i]*tw[i]);
    }
}

// ---------------- SpMM: warp per destination node ----------------
__global__ void spmm_kernel(const float* __restrict__ curr_h){
    int w = (blockIdx.x*blockDim.x + threadIdx.x) >> 5;
    int lane = threadIdx.x & 31;
    if (w >= NN) return;
    const float4* ch4 = (const float4*)curr_h;
    const float4* xf4 = (const float4*)g_xf;
    float sw = g_rs_out[w];
    float4 ac = ch4[w*32 + lane];
    float4 af = xf4[w*32 + lane];
    ac.x*=sw; ac.y*=sw; ac.z*=sw; ac.w*=sw;
    af.x*=sw; af.y*=sw; af.z*=sw; af.w*=sw;
    int s0 = g_row_ptr[w], s1 = g_row_ptr[w+1];
    int base = s0;
    for (; base + 32 <= s1; base += 32){
        int sv = g_csr[base + lane];
        float fv = g_rs_out[sv];
        #pragma unroll 8
        for (int j=0;j<32;j++){
            int   s  = __shfl_sync(0xffffffffu, sv, j);
            float sc = __shfl_sync(0xffffffffu, fv, j);
            float4 vc = ch4[s*32+lane], vf = xf4[s*32+lane];
            ac.x = fmaf(vc.x, sc, ac.x); ac.y = fmaf(vc.y, sc, ac.y);
            ac.z = fmaf(vc.z, sc, ac.z); ac.w = fmaf(vc.w, sc, ac.w);
            af.x = fmaf(vf.x, sc, af.x); af.y = fmaf(vf.y, sc, af.y);
            af.z = fmaf(vf.z, sc, af.z); af.w = fmaf(vf.w, sc, af.w);
        }
    }
    int rem = s1 - base;
    if (rem > 0){
        int   sv = (lane < rem) ? g_csr[base + lane] : 0;
        float fv = g_rs_out[sv];
        for (int j=0;j<rem;j++){
            int   s  = __shfl_sync(0xffffffffu, sv, j);
            float sc = __shfl_sync(0xffffffffu, fv, j);
            float4 vc = ch4[s*32+lane], vf = xf4[s*32+lane];
            ac.x = fmaf(vc.x, sc, ac.x); ac.y = fmaf(vc.y, sc, ac.y);
            ac.z = fmaf(vc.z, sc, ac.z); ac.w = fmaf(vc.w, sc, ac.w);
            af.x = fmaf(vf.x, sc, af.x); af.y = fmaf(vf.y, sc, af.y);
            af.z = fmaf(vf.z, sc, af.z); af.w = fmaf(vf.w, sc, af.w);
        }
    }
    float ri = g_rs_in[w];
    ac.x*=ri; ac.y*=ri; ac.z*=ri; ac.w*=ri;
    af.x*=ri; af.y*=ri; af.z*=ri; af.w*=ri;
    float4* agg4 = (float4*)g_agg;
    agg4[w*64 + lane]      = ac;
    agg4[w*64 + 32 + lane] = af;
}

// ========================================================================
// GEMM1: g_xf[16384,128] = curr_inc[16384,8192] @ nh^T    (unscaled)
// BM=64, BK=64, 2-stage double buffer, 2 CTAs/SM, grid=256.
// 8 warps in 2x4 grid: each warp 32 rows x 32 cols.
// ========================================================================
__global__ void __launch_bounds__(256,2) gemm1_k(const float* __restrict__ A,
                                                 float* __restrict__ C){
    extern __shared__ float sm[];
    const int tid = threadIdx.x, lane = tid & 31, wid = tid >> 5;
    const int wm = wid & 1, wn = wid >> 1;     // 2x4 warps: 32 rows x 32 cols each
    const int g = lane >> 2, t = lane & 3;
    const long long brow = (long long)blockIdx.x * BM1;

    float acc[2][4][4];
    #pragma unroll
    for (int i=0;i<2;i++)
        #pragma unroll
        for (int j=0;j<4;j++)
            #pragma unroll
            for (int l=0;l<4;l++) acc[i][j][l] = 0.f;

    auto load_stage = [&](int s, int m){
        if (m < NK1){
            float* as = sm + s*STG1_FLOATS;
            float* bs = as + A1_FLOATS;
            #pragma unroll
            for (int i=0;i<4;i++){                     // A: 64 rows x 64 floats = 1024 x 16B
                int id = tid + i*256;
                int r = id >> 4, c = (id & 15) * 4;
                cp16(as + r*A1_PITCH + c, A + (brow + r)*MM + m*BK1 + c);
            }
            const float* pb = g_pb + (size_t)m*B1_FLOATS;
            #pragma unroll
            for (int i=0;i<8;i++){                     // B: 2048 x 16B straight copy
                int id = tid + i*256;
                cp16(bs + id*4, pb + id*4);
            }
        }
        asm volatile("cp.async.commit_group;\n" ::: "memory");
    };

    load_stage(0,0);

    for (int m=0; m<NK1; m++){
        int s = m & 1;
        load_stage(s^1, m+1);
        asm volatile("cp.async.wait_group 1;\n" ::: "memory");
        __syncthreads();
        const float* as = sm + s*STG1_FLOATS;
        const float* bs = as + A1_FLOATS;
        #pragma unroll
        for (int kk=0; kk<BK1; kk+=8){
            uint32_t af[2][4];
            #pragma unroll
            for (int mt=0; mt<2; mt++){
                int r0 = wm*32 + mt*16 + g;
                af[mt][0] = f2tf(as[ r0     *A1_PITCH + kk + t    ]);
                af[mt][1] = f2tf(as[(r0 + 8)*A1_PITCH + kk + t    ]);
                af[mt][2] = f2tf(as[ r0     *A1_PITCH + kk + t + 4]);
                af[mt][3] = f2tf(as[(r0 + 8)*A1_PITCH + kk + t + 4]);
            }
            const float* bk = bs + (kk >> 5)*4096 + ((kk >> 3) & 3)*1024 + lane*2;
            #pragma unroll
            for (int nt=0; nt<4; nt++){
                float2 b2 = *(const float2*)(bk + (wn*4 + nt)*64);
                uint32_t b0 = __float_as_uint(b2.x);
                uint32_t b1 = __float_as_uint(b2.y);
                mma8(acc[0][nt], af[0], b0, b1);
                mma8(acc[1][nt], af[1], b0, b1);
            }
        }
        __syncthreads();
    }

    // epilogue: store raw accumulators (rowscale applied later in spmm)
    #pragma unroll
    for (int mt=0; mt<2; mt++){
        int r0 = (int)brow + wm*32 + mt*16 + g;
        #pragma unroll
        for (int nt=0; nt<4; nt++){
            int c0 = wn*32 + nt*8 + 2*t;
            float2 v0 = { acc[mt][nt][0], acc[mt][nt][1] };
            float2 v1 = { acc[mt][nt][2], acc[mt][nt][3] };
            *(float2*)(C + (size_t) r0   *DD + c0) = v0;
            *(float2*)(C + (size_t)(r0+8)*DD + c0) = v1;
        }
    }
}

// ========================================================================
// GEMM2: out = relu(LN(g_agg[16384,256] @ g_wcat[256,128] + b2)*gamma+beta)
// ========================================================================
__global__ void __launch_bounds__(256,1) gemm2_kernel(
    const float* __restrict__ A, const float* __restrict__ B, float* __restrict__ C,
    const float* __restrict__ bias, const float* __restrict__ gamma,
    const float* __restrict__ beta)
{
    extern __shared__ float smem[];
    float* As = smem;
    float* Bs = smem + 2*BM*AST;
    const int tid = threadIdx.x, lane = tid & 31, wid = tid >> 5;
    const int wm = wid & 3, wn = wid >> 2;
    const int g = lane >> 2, t = lane & 3;
    const long long brow = (long long)blockIdx.x * BM;
    const int K = 2*DD;

    float acc[2][8][4];
    #pragma unroll
    for (int i=0;i<2;i++)
        #pragma unroll
        for (int j=0;j<8;j++)
            #pragma unroll
            for (int l=0;l<4;l++) acc[i][j][l] = 0.f;

    const int KT = K / BK;   // 8

    auto load_tile = [&](int buf, int kt){
        const int k0 = kt * BK;
        float* as = As + buf*BM*AST;
        float* bs = Bs + buf*BK*BST;
        #pragma unroll
        for (int i=0;i<4;i++){
            int id = tid + i*256;
            int r = id >> 3, c = (id & 7) * 4;
            cp16(as + r*AST + c, A + (brow + r)*K + k0 + c);
        }
        #pragma unroll
        for (int i=0;i<4;i++){
            int id = tid + i*256;
            int r = id >> 5, c = (id & 31) * 4;
            cp16(bs + r*BST + c, B + (long long)(k0 + r)*BN + c);
        }
        asm volatile("cp.async.commit_group;\n");
    };

    load_tile(0, 0);
    for (int kt=0; kt<KT; kt++){
        int cur = kt & 1;
        if (kt + 1 < KT){
            load_tile(cur^1, kt+1);
            asm volatile("cp.async.wait_group 1;\n");
        } else {
            asm volatile("cp.async.wait_group 0;\n");
        }
        __syncthreads();
        const float* as = As + cur*BM*AST;
        const float* bs = Bs + cur*BK*BST;
        #pragma unroll
        for (int kk=0; kk<BK; kk+=8){
            uint32_t af[2][4];
            #pragma unroll
            for (int mt=0; mt<2; mt++){
                int r0 = wm*32 + mt*16 + g;
                af[mt][0] = f2tf(as[ r0     *AST + kk + t    ]);
                af[mt][1] = f2tf(as[(r0 + 8)*AST + kk + t    ]);
                af[mt][2] = f2tf(as[ r0     *AST + kk + t + 4]);
                af[mt][3] = f2tf(as[(r0 + 8)*AST + kk + t + 4]);
            }
            #pragma unroll
            for (int nt=0; nt<8; nt++){
                int c0 = wn*64 + nt*8 + g;
                uint32_t b0 = __float_as_uint(bs[(kk + t    )*BST + c0]);
                uint32_t b1 = __float_as_uint(bs[(kk + t + 4)*BST + c0]);
                mma8(acc[0][nt], af[0], b0, b1);
                mma8(acc[1][nt], af[1], b0, b1);
            }
        }
        __syncthreads();
    }

    // fused bias + LayerNorm + ReLU via smem staging
    float* sm = smem;
    #pragma unroll
    for (int mt=0; mt<2; mt++){
        int r0 = wm*32 + mt*16 + g;
        #pragma unroll
        for (int nt=0; nt<8; nt++){
            int c0 = wn*64 + nt*8 + 2*t;
            sm[ r0   *EPI_PITCH + c0    ] = acc[mt][nt][0];
            sm[ r0   *EPI_PITCH + c0 + 1] = acc[mt][nt][1];
            sm[(r0+8)*EPI_PITCH + c0    ] = acc[mt][nt][2];
            sm[(r0+8)*EPI_PITCH + c0 + 1] = acc[mt][nt][3];
        }
    }
    __syncthreads();
    if (tid < 128){
        int r = tid;
        float s = 0.f, s2 = 0.f;
        #pragma unroll 8
        for (int c=0;c<128;c++){
            float v = sm[r*EPI_PITCH + c] + bias[c];
            s += v; s2 += v*v;
        }
        float mu   = s  * (1.f/128.f);
        float var  = s2 * (1.f/128.f) - mu*mu;
        float rstd = rsqrtf(var + 1e-5f);
        long long ro = (brow + r) * 128;
        #pragma unroll 8
        for (int c=0;c<128;c++){
            float v = sm[r*EPI_PITCH + c] + bias[c];
            float o = (v - mu)*rstd*gamma[c] + beta[c];
            C[ro + c] = fmaxf(o, 0.f);
        }
    }
}

// ---------------- launcher ----------------
extern "C" void kernel_launch(void* const* d_in, const int* in_sizes, int n_in,
                              void* d_out, int out_size){
    const float* curr_h   = (const float*)d_in[0];
    const float* next_h   = (const float*)d_in[1];
    const float* curr_inc = (const float*)d_in[2];
    const float* Wc    = (const float*)d_in[3];
    const float* bc    = (const float*)d_in[4];
    const float* Wf    = (const float*)d_in[5];
    const float* bf    = (const float*)d_in[6];
    const float* cw    = (const float*)d_in[7];
    const float* tw    = (const float*)d_in[8];
    const float* gamma = (const float*)d_in[9];
    const float* beta  = (const float*)d_in[10];
    const int* esrc = (const int*)d_in[11];
    const int* edst = (const int*)d_in[12];
    float* out = (float*)d_out;

    void *p_xf, *p_agg, *p_wcat, *p_b2;
    cudaGetSymbolAddress(&p_xf,   g_xf);
    cudaGetSymbolAddress(&p_agg,  g_agg);
    cudaGetSymbolAddress(&p_wcat, g_wcat);
    cudaGetSymbolAddress(&p_b2,   g_b2);

    cudaFuncSetAttribute(gemm1_k,      cudaFuncAttributeMaxDynamicSharedMemorySize, GEMM1_SMEM);
    cudaFuncSetAttribute(gemm2_kernel, cudaFuncAttributeMaxDynamicSharedMemorySize, SMEM_BYTES);

    // gemm1_k kept in launch slot 4 (the slot ncu captures).
    pack_b_kernel <<<1024, 512>>>(next_h);                         // 1
    zero_kernel   <<<64,   256>>>();                               // 2
    degree_kernel <<<2048, 256>>>(esrc, edst);                     // 3
    gemm1_k       <<<256,  256, GEMM1_SMEM>>>(curr_inc, (float*)p_xf);  // 4  <- profiled
    scan_kernel   <<<1,   1024>>>();                               // 5
    scatter_kernel<<<2048, 256>>>(esrc, edst);                     // 6
    prep_kernel   <<<128,  256>>>(Wc, bc, Wf, bf, cw, tw);         // 7
    spmm_kernel   <<<2048, 256>>>(curr_h);                         // 8
    gemm2_kernel  <<<128,  256, SMEM_BYTES>>>((const float*)p_agg, (const float*)p_wcat,
                                              out, (const float*)p_b2, gamma, beta);  // 9
}

// round 14
// speedup vs baseline: 1.5501x; 1.5501x over previous
#include <cuda_runtime.h>
#include <cstdint>

#define NN 16384
#define MM 8192
#define EE 524288
#define DD 128

// ==== GEMM1: BM=128, split-K x2 (K=4096/CTA), BK=32, 3-stage, 2 CTAs/SM ====
#define BK1 32
#define NK1 ((MM/2)/BK1)             // 128 K-stages per CTA (half K)
#define A1_PITCH 36                  // A smem pitch (floats): conflict-free frags
#define A1_FLOATS (128*A1_PITCH)     // 4608
#define B1_FLOATS 4096               // packed B per 32-K tile (16KB)
#define STG1_FLOATS (A1_FLOATS + B1_FLOATS)   // 8704
#define GEMM1_SMEM (3*STG1_FLOATS*4)          // 104448 B -> 2 CTAs/SM
#define PB_F2 ((size_t)(MM/32)*2048)          // 524288 float2 total

// ================= GEMM2 (mma.sync) tiling =================
#define BM 128
#define BN 128
#define BK 32
#define AST 36
#define BST 132
#define SMEM_FLOATS (2*BM*AST + 2*BK*BST)
#define SMEM_BYTES  (SMEM_FLOATS*4)
#define EPI_PITCH 133

// ---------------- device scratch (static, no allocation) ----------------
__device__ int   g_out_cnt[NN];
__device__ int   g_in_cnt[NN];
__device__ int   g_cursor[NN];
__device__ int   g_row_ptr[NN+1];
__device__ int   g_csr[EE];
__device__ float g_rs_out[NN];
__device__ float g_rs_in[NN];
__device__ float g_xfa[NN*DD];         // split-K half 0 partial
__device__ float g_xfb[NN*DD];         // split-K half 1 partial
__device__ float g_xf[NN*DD];          // xfa + xfb (unscaled; rs_out applied in spmm)
__device__ float g_agg[NN*2*DD];       // [aggc | aggf]
__device__ float g_pb[(size_t)(MM/32)*4096];   // next_h fragment-packed, rna (4MB)
__device__ float g_wcat[2*DD*DD];
__device__ float g_b2[DD];

// ---------------- helpers ----------------
__device__ __forceinline__ uint32_t f2tf(float x){
    uint32_t r; asm("cvt.rna.tf32.f32 %0, %1;" : "=r"(r) : "f"(x)); return r;
}
__device__ __forceinline__ float rnaf(float x){ return __uint_as_float(f2tf(x)); }
__device__ __forceinline__ void cp16(float* s, const float* g){
    unsigned sa = (unsigned)__cvta_generic_to_shared(s);
    asm volatile("cp.async.cg.shared.global [%0], [%1], 16;\n" :: "r"(sa), "l"(g));
}
__device__ __forceinline__ void mma8(float* c, const uint32_t* a, uint32_t b0, uint32_t b1){
    asm volatile("mma.sync.aligned.m16n8k8.row.col.f32.tf32.tf32.f32 "
        "{%0,%1,%2,%3},{%4,%5,%6,%7},{%8,%9},{%0,%1,%2,%3};\n"
        : "+f"(c[0]),"+f"(c[1]),"+f"(c[2]),"+f"(c[3])
        : "r"(a[0]),"r"(a[1]),"r"(a[2]),"r"(a[3]),"r"(b0),"r"(b1));
}

// ---------------- small kernels ----------------
__global__ void zero_kernel(){
    int i = blockIdx.x*blockDim.x + threadIdx.x;
    if (i < NN){ g_out_cnt[i]=0; g_in_cnt[i]=0; g_cursor[i]=0; }
}

__global__ void degree_kernel(const int* __restrict__ src, const int* __restrict__ dst){
    int e = blockIdx.x*blockDim.x + threadIdx.x;
    if (e < EE){ atomicAdd(&g_out_cnt[src[e]],1); atomicAdd(&g_in_cnt[dst[e]],1); }
}

__global__ void scan_kernel(){
    __shared__ int ssum[1024];
    int tid = threadIdx.x;
    int loc[16]; int sum = 0;
    #pragma unroll
    for (int j=0;j<16;j++){ loc[j] = g_in_cnt[tid*16+j]; sum += loc[j]; }
    ssum[tid] = sum; __syncthreads();
    for (int off=1; off<1024; off<<=1){
        int v = (tid >= off) ? ssum[tid-off] : 0;
        __syncthreads();
        ssum[tid] += v;
        __syncthreads();
    }
    int run = ssum[tid] - sum;
    #pragma unroll
    for (int j=0;j<16;j++){ g_row_ptr[tid*16+j] = run; run += loc[j]; }
    if (tid == 1023) g_row_ptr[NN] = run;
    for (int i=tid; i<NN; i+=1024){
        g_rs_in[i]  = rsqrtf((float)g_in_cnt[i]  + 1.f);
        g_rs_out[i] = rsqrtf((float)g_out_cnt[i] + 1.f);
    }
}

__global__ void scatter_kernel(const int* __restrict__ src, const int* __restrict__ dst){
    int e = blockIdx.x*blockDim.x + threadIdx.x;
    if (e < EE){
        int d = dst[e];
        int p = g_row_ptr[d] + atomicAdd(&g_cursor[d], 1);
        g_csr[p] = src[e];
    }
}

// Pack next_h [K=8192, N=128] into mma-fragment order, tf32-rna.
__global__ void pack_b_kernel(const float* __restrict__ nh){
    size_t idx = (size_t)blockIdx.x*blockDim.x + threadIdx.x;
    if (idx >= PB_F2) return;
    int lane = (int)(idx & 31);
    int ct   = (int)((idx >> 5) & 15);
    int kk4  = (int)((idx >> 9) & 3);
    int kt   = (int)(idx >> 11);
    int k0 = kt*32 + kk4*8 + (lane & 3);
    int n  = ct*8 + (lane >> 2);
    float2 v;
    v.x = rnaf(nh[(size_t)k0*DD + n]);
    v.y = rnaf(nh[(size_t)(k0+4)*DD + n]);
    ((float2*)g_pb)[idx] = v;
}

__global__ void prep_kernel(const float* __restrict__ Wc, const float* __restrict__ bc,
                            const float* __restrict__ Wf, const float* __restrict__ bf,
                            const float* __restrict__ cw, const float* __restrict__ tw){
    int i = blockIdx.x*blockDim.x + threadIdx.x;
    if (i < 2*DD*DD){
        int k = i >> 7, j = i & 127;
        float w = (k < DD) ? Wc[k*DD+j]*cw[j] : Wf[(k-DD)*DD+j]*tw[j];
        g_wcat[i] = __uint_as_float(f2tf(0.5f*w));
        if (i < DD) g_b2[i] = 0.5f*(bc[i]*cw[i] + bf[i]*tw[i]);
    }
}

// combine split-K halves: g_xf = g_xfa + g_xfb
__global__ void reduce_xf(){
    int i = blockIdx.x*blockDim.x + threadIdx.x;
    if (i < NN*DD/4){
        float4 a = ((const float4*)g_xfa)[i];
        float4 b = ((const float4*)g_xfb)[i];
        a.x+=b.x; a.y+=b.y; a.z+=b.z; a.w+=b.w;
        ((float4*)g_xf)[i] = a;
    }
}

// ---------------- SpMM: warp per destination node ----------------
__global__ void spmm_kernel(const float* __restrict__ curr_h){
    int w = (blockIdx.x*blockDim.x + threadIdx.x) >> 5;
    int lane = threadIdx.x & 31;
    if (w >= NN) return;
    const float4* ch4 = (const float4*)curr_h;
    const float4* xf4 = (const float4*)g_xf;
    float sw = g_rs_out[w];
    float4 ac = ch4[w*32 + lane];
    float4 af = xf4[w*32 + lane];
    ac.x*=sw; ac.y*=sw; ac.z*=sw; ac.w*=sw;
    af.x*=sw; af.y*=sw; af.z*=sw; af.w*=sw;
    int s0 = g_row_ptr[w], s1 = g_row_ptr[w+1];
    int base = s0;
    for (; base + 32 <= s1; base += 32){
        int sv = g_csr[base + lane];
        float fv = g_rs_out[sv];
        #pragma unroll 8
        for (int j=0;j<32;j++){
            int   s  = __shfl_sync(0xffffffffu, sv, j);
            float sc = __shfl_sync(0xffffffffu, fv, j);
            float4 vc = ch4[s*32+lane], vf = xf4[s*32+lane];
            ac.x = fmaf(vc.x, sc, ac.x); ac.y = fmaf(vc.y, sc, ac.y);
            ac.z = fmaf(vc.z, sc, ac.z); ac.w = fmaf(vc.w, sc, ac.w);
            af.x = fmaf(vf.x, sc, af.x); af.y = fmaf(vf.y, sc, af.y);
            af.z = fmaf(vf.z, sc, af.z); af.w = fmaf(vf.w, sc, af.w);
        }
    }
    int rem = s1 - base;
    if (rem > 0){
        int   sv = (lane < rem) ? g_csr[base + lane] : 0;
        float fv = g_rs_out[sv];
        for (int j=0;j<rem;j++){
            int   s  = __shfl_sync(0xffffffffu, sv, j);
            float sc = __shfl_sync(0xffffffffu, fv, j);
            float4 vc = ch4[s*32+lane], vf = xf4[s*32+lane];
            ac.x = fmaf(vc.x, sc, ac.x); ac.y = fmaf(vc.y, sc, ac.y);
            ac.z = fmaf(vc.z, sc, ac.z); ac.w = fmaf(vc.w, sc, ac.w);
            af.x = fmaf(vf.x, sc, af.x); af.y = fmaf(vf.y, sc, af.y);
            af.z = fmaf(vf.z, sc, af.z); af.w = fmaf(vf.w, sc, af.w);
        }
    }
    float ri = g_rs_in[w];
    ac.x*=ri; ac.y*=ri; ac.z*=ri; ac.w*=ri;
    af.x*=ri; af.y*=ri; af.z*=ri; af.w*=ri;
    float4* agg4 = (float4*)g_agg;
    agg4[w*64 + lane]      = ac;
    agg4[w*64 + 32 + lane] = af;
}

// ========================================================================
// GEMM1 split-K: partial[khalf][16384,128] = A[:, khalf*4096 + 0:4096] @ nh^T
// BM=128, BK=32, 3-stage ring, 2 CTAs/SM, grid=256 (bid&1 = khalf).
// 8 warps in 4x2 grid: each warp 32 rows x 64 cols (R12-proven geometry).
// ========================================================================
__global__ void __launch_bounds__(256,2) gemm1_k(const float* __restrict__ A,
                                                 float* __restrict__ Ca,
                                                 float* __restrict__ Cb){
    extern __shared__ float sm[];
    const int tid = threadIdx.x, lane = tid & 31, wid = tid >> 5;
    const int wm = wid & 3, wn = wid >> 2;     // 4x2 warps: 32 rows x 64 cols each
    const int g = lane >> 2, t = lane & 3;
    const int khalf = blockIdx.x & 1;
    const long long brow = (long long)(blockIdx.x >> 1) * 128;
    const long long kof  = (long long)khalf * (MM/2);
    const int kt0 = khalf * NK1;               // packed-B 32-tile base
    float* Cout = khalf ? Cb : Ca;

    float acc[2][8][4];
    #pragma unroll
    for (int i=0;i<2;i++)
        #pragma unroll
        for (int j=0;j<8;j++)
            #pragma unroll
            for (int l=0;l<4;l++) acc[i][j][l] = 0.f;

    auto load_stage = [&](int s, int m){
        if (m < NK1){
            float* as = sm + s*STG1_FLOATS;
            float* bs = as + A1_FLOATS;
            #pragma unroll
            for (int i=0;i<4;i++){                     // A: 128 rows x 32 floats = 1024 x 16B
                int id = tid + i*256;
                int r = id >> 3, c = (id & 7) * 4;
                cp16(as + r*A1_PITCH + c, A + (brow + r)*MM + kof + m*BK1 + c);
            }
            const float* pb = g_pb + (size_t)(kt0 + m)*B1_FLOATS;
            #pragma unroll
            for (int i=0;i<4;i++){                     // B: 1024 x 16B straight copy
                int id = tid + i*256;
                cp16(bs + id*4, pb + id*4);
            }
        }
        asm volatile("cp.async.commit_group;\n" ::: "memory");
    };

    load_stage(0,0); load_stage(1,1);

    for (int m=0; m<NK1; m++){
        int s = m % 3;
        load_stage((m+2)%3, m+2);
        asm volatile("cp.async.wait_group 2;\n" ::: "memory");
        __syncthreads();
        const float* as = sm + s*STG1_FLOATS;
        const float* bs = as + A1_FLOATS;
        #pragma unroll
        for (int kk=0; kk<BK1; kk+=8){
            uint32_t af[2][4];
            #pragma unroll
            for (int mt=0; mt<2; mt++){
                int r0 = wm*32 + mt*16 + g;
                af[mt][0] = f2tf(as[ r0     *A1_PITCH + kk + t    ]);
                af[mt][1] = f2tf(as[(r0 + 8)*A1_PITCH + kk + t    ]);
                af[mt][2] = f2tf(as[ r0     *A1_PITCH + kk + t + 4]);
                af[mt][3] = f2tf(as[(r0 + 8)*A1_PITCH + kk + t + 4]);
            }
            const float* bk = bs + (kk >> 3)*1024 + lane*2;
            #pragma unroll
            for (int nt=0; nt<8; nt++){
                float2 b2 = *(const float2*)(bk + (wn*8 + nt)*64);
                uint32_t b0 = __float_as_uint(b2.x);
                uint32_t b1 = __float_as_uint(b2.y);
                mma8(acc[0][nt], af[0], b0, b1);
                mma8(acc[1][nt], af[1], b0, b1);
            }
        }
        __syncthreads();
    }

    // epilogue: store raw partial accumulators
    #pragma unroll
    for (int mt=0; mt<2; mt++){
        int r0 = (int)brow + wm*32 + mt*16 + g;
        #pragma unroll
        for (int nt=0; nt<8; nt++){
            int c0 = wn*64 + nt*8 + 2*t;
            float2 v0 = { acc[mt][nt][0], acc[mt][nt][1] };
            float2 v1 = { acc[mt][nt][2], acc[mt][nt][3] };
            *(float2*)(Cout + (size_t) r0   *DD + c0) = v0;
            *(float2*)(Cout + (size_t)(r0+8)*DD + c0) = v1;
        }
    }
}

// ========================================================================
// GEMM2: out = relu(LN(g_agg[16384,256] @ g_wcat[256,128] + b2)*gamma+beta)
// ========================================================================
__global__ void __launch_bounds__(256,1) gemm2_kernel(
    const float* __restrict__ A, const float* __restrict__ B, float* __restrict__ C,
    const float* __restrict__ bias, const float* __restrict__ gamma,
    const float* __restrict__ beta)
{
    extern __shared__ float smem[];
    float* As = smem;
    float* Bs = smem + 2*BM*AST;
    const int tid = threadIdx.x, lane = tid & 31, wid = tid >> 5;
    const int wm = wid & 3, wn = wid >> 2;
    const int g = lane >> 2, t = lane & 3;
    const long long brow = (long long)blockIdx.x * BM;
    const int K = 2*DD;

    float acc[2][8][4];
    #pragma unroll
    for (int i=0;i<2;i++)
        #pragma unroll
        for (int j=0;j<8;j++)
            #pragma unroll
            for (int l=0;l<4;l++) acc[i][j][l] = 0.f;

    const int KT = K / BK;   // 8

    auto load_tile = [&](int buf, int kt){
        const int k0 = kt * BK;
        float* as = As + buf*BM*AST;
        float* bs = Bs + buf*BK*BST;
        #pragma unroll
        for (int i=0;i<4;i++){
            int id = tid + i*256;
            int r = id >> 3, c = (id & 7) * 4;
            cp16(as + r*AST + c, A + (brow + r)*K + k0 + c);
        }
        #pragma unroll
        for (int i=0;i<4;i++){
            int id = tid + i*256;
            int r = id >> 5, c = (id & 31) * 4;
            cp16(bs + r*BST + c, B + (long long)(k0 + r)*BN + c);
        }
        asm volatile("cp.async.commit_group;\n");
    };

    load_tile(0, 0);
    for (int kt=0; kt<KT; kt++){
        int cur = kt & 1;
        if (kt + 1 < KT){
            load_tile(cur^1, kt+1);
            asm volatile("cp.async.wait_group 1;\n");
        } else {
            asm volatile("cp.async.wait_group 0;\n");
        }
        __syncthreads();
        const float* as = As + cur*BM*AST;
        const float* bs = Bs + cur*BK*BST;
        #pragma unroll
        for (int kk=0; kk<BK; kk+=8){
            uint32_t af[2][4];
            #pragma unroll
            for (int mt=0; mt<2; mt++){
                int r0 = wm*32 + mt*16 + g;
                af[mt][0] = f2tf(as[ r0     *AST + kk + t    ]);
                af[mt][1] = f2tf(as[(r0 + 8)*AST + kk + t    ]);
                af[mt][2] = f2tf(as[ r0     *AST + kk + t + 4]);
                af[mt][3] = f2tf(as[(r0 + 8)*AST + kk + t + 4]);
            }
            #pragma unroll
            for (int nt=0; nt<8; nt++){
                int c0 = wn*64 + nt*8 + g;
                uint32_t b0 = __float_as_uint(bs[(kk + t    )*BST + c0]);
                uint32_t b1 = __float_as_uint(bs[(kk + t + 4)*BST + c0]);
                mma8(acc[0][nt], af[0], b0, b1);
                mma8(acc[1][nt], af[1], b0, b1);
            }
        }
        __syncthreads();
    }

    // fused bias + LayerNorm + ReLU via smem staging
    float* sm = smem;
    #pragma unroll
    for (int mt=0; mt<2; mt++){
        int r0 = wm*32 + mt*16 + g;
        #pragma unroll
        for (int nt=0; nt<8; nt++){
            int c0 = wn*64 + nt*8 + 2*t;
            sm[ r0   *EPI_PITCH + c0    ] = acc[mt][nt][0];
            sm[ r0   *EPI_PITCH + c0 + 1] = acc[mt][nt][1];
            sm[(r0+8)*EPI_PITCH + c0    ] = acc[mt][nt][2];
            sm[(r0+8)*EPI_PITCH + c0 + 1] = acc[mt][nt][3];
        }
    }
    __syncthreads();
    if (tid < 128){
        int r = tid;
        float s = 0.f, s2 = 0.f;
        #pragma unroll 8
        for (int c=0;c<128;c++){
            float v = sm[r*EPI_PITCH + c] + bias[c];
            s += v; s2 += v*v;
        }
        float mu   = s  * (1.f/128.f);
        float var  = s2 * (1.f/128.f) - mu*mu;
        float rstd = rsqrtf(var + 1e-5f);
        long long ro = (brow + r) * 128;
        #pragma unroll 8
        for (int c=0;c<128;c++){
            float v = sm[r*EPI_PITCH + c] + bias[c];
            float o = (v - mu)*rstd*gamma[c] + beta[c];
            C[ro + c] = fmaxf(o, 0.f);
        }
    }
}

// ---------------- launcher ----------------
extern "C" void kernel_launch(void* const* d_in, const int* in_sizes, int n_in,
                              void* d_out, int out_size){
    const float* curr_h   = (const float*)d_in[0];
    const float* next_h   = (const float*)d_in[1];
    const float* curr_inc = (const float*)d_in[2];
    const float* Wc    = (const float*)d_in[3];
    const float* bc    = (const float*)d_in[4];
    const float* Wf    = (const float*)d_in[5];
    const float* bf    = (const float*)d_in[6];
    const float* cw    = (const float*)d_in[7];
    const float* tw    = (const float*)d_in[8];
    const float* gamma = (const float*)d_in[9];
    const float* beta  = (const float*)d_in[10];
    const int* esrc = (const int*)d_in[11];
    const int* edst = (const int*)d_in[12];
    float* out = (float*)d_out;

    void *p_xfa, *p_xfb, *p_agg, *p_wcat, *p_b2;
    cudaGetSymbolAddress(&p_xfa,  g_xfa);
    cudaGetSymbolAddress(&p_xfb,  g_xfb);
    cudaGetSymbolAddress(&p_agg,  g_agg);
    cudaGetSymbolAddress(&p_wcat, g_wcat);
    cudaGetSymbolAddress(&p_b2,   g_b2);

    cudaFuncSetAttribute(gemm1_k,      cudaFuncAttributeMaxDynamicSharedMemorySize, GEMM1_SMEM);
    cudaFuncSetAttribute(gemm2_kernel, cudaFuncAttributeMaxDynamicSharedMemorySize, SMEM_BYTES);

    // gemm1_k kept in launch slot 4 (the slot ncu captures).
    pack_b_kernel <<<1024, 512>>>(next_h);                         // 1
    zero_kernel   <<<64,   256>>>();                               // 2
    degree_kernel <<<2048, 256>>>(esrc, edst);                     // 3
    gemm1_k       <<<256,  256, GEMM1_SMEM>>>(curr_inc, (float*)p_xfa, (float*)p_xfb); // 4 <- profiled
    scan_kernel   <<<1,   1024>>>();                               // 5
    scatter_kernel<<<2048, 256>>>(esrc, edst);                     // 6
    reduce_xf     <<<2048, 256>>>();                               // 7
    prep_kernel   <<<128,  256>>>(Wc, bc, Wf, bf, cw, tw);         // 8
    spmm_kernel   <<<2048, 256>>>(curr_h);                         // 9
    gemm2_kernel  <<<128,  256, SMEM_BYTES>>>((const float*)p_agg, (const float*)p_wcat,
                                              out, (const float*)p_b2, gamma, beta);  // 10
}

// round 17
// speedup vs baseline: 1.8036x; 1.1635x over previous
#include <cuda_runtime.h>
#include <cstdint>

#define NN 16384
#define MM 8192
#define EE 524288
#define DD 128

// ==== GEMM1: BM=128, split-K x2 (K=4096/CTA), BK=32, 3-stage, 2 CTAs/SM ====
#define BK1 32
#define NK1 ((MM/2)/BK1)             // 128 K-stages per CTA (half K)
#define A1_PITCH 36                  // A smem pitch (floats): conflict-free frags
#define A1_FLOATS (128*A1_PITCH)     // 4608
#define B1_FLOATS 4096               // packed B per 32-K tile (16KB)
#define STG1_FLOATS (A1_FLOATS + B1_FLOATS)   // 8704
#define GEMM1_SMEM (3*STG1_FLOATS*4)          // 104448 B -> 2 CTAs/SM
#define PB_F2 ((size_t)(MM/32)*2048)          // 524288 float2 total

// ================= GEMM2 (mma.sync) tiling =================
#define BM 128
#define BN 128
#define BK 32
#define AST 36
#define BST 132
#define SMEM_FLOATS (2*BM*AST + 2*BK*BST)
#define SMEM_BYTES  (SMEM_FLOATS*4)
#define EPI_PITCH 133

// ---------------- device scratch (static, no allocation) ----------------
__device__ int   g_out_cnt[NN];
__device__ int   g_in_cnt[NN];
__device__ int   g_cursor[NN];
__device__ int   g_row_ptr[NN+1];
__device__ int   g_csr[EE];
__device__ float g_rs_out[NN];
__device__ float g_rs_in[NN];
__device__ float g_xfa[NN*DD];         // split-K half 0 partial
__device__ float g_xfb[NN*DD];         // split-K half 1 partial
__device__ float g_xf[NN*DD];          // xfa + xfb (unscaled; rs_out applied in spmm)
__device__ float g_agg[NN*2*DD];       // [aggc | aggf]
__device__ float g_pb[(size_t)(MM/32)*4096];   // next_h fragment-packed, rna (4MB)
__device__ float g_wcat[2*DD*DD];
__device__ float g_b2[DD];

// ---------------- helpers ----------------
__device__ __forceinline__ uint32_t f2tf(float x){
    uint32_t r; asm("cvt.rna.tf32.f32 %0, %1;" : "=r"(r) : "f"(x)); return r;
}
__device__ __forceinline__ float rnaf(float x){ return __uint_as_float(f2tf(x)); }
__device__ __forceinline__ void cp16(float* s, const float* g){
    unsigned sa = (unsigned)__cvta_generic_to_shared(s);
    asm volatile("cp.async.cg.shared.global [%0], [%1], 16;\n" :: "r"(sa), "l"(g));
}
__device__ __forceinline__ void mma8(float* c, const uint32_t* a, uint32_t b0, uint32_t b1){
    asm volatile("mma.sync.aligned.m16n8k8.row.col.f32.tf32.tf32.f32 "
        "{%0,%1,%2,%3},{%4,%5,%6,%7},{%8,%9},{%0,%1,%2,%3};\n"
        : "+f"(c[0]),"+f"(c[1]),"+f"(c[2]),"+f"(c[3])
        : "r"(a[0]),"r"(a[1]),"r"(a[2]),"r"(a[3]),"r"(b0),"r"(b1));
}

// ---------------- small kernels ----------------
__global__ void zero_kernel(){
    int i = blockIdx.x*blockDim.x + threadIdx.x;
    if (i < NN){ g_out_cnt[i]=0; g_in_cnt[i]=0; g_cursor[i]=0; }
}

__global__ void degree_kernel(const int* __restrict__ src, const int* __restrict__ dst){
    int e = blockIdx.x*blockDim.x + threadIdx.x;
    if (e < EE){ atomicAdd(&g_out_cnt[src[e]],1); atomicAdd(&g_in_cnt[dst[e]],1); }
}

__global__ void scan_kernel(){
    __shared__ int ssum[1024];
    int tid = threadIdx.x;
    int loc[16]; int sum = 0;
    #pragma unroll
    for (int j=0;j<16;j++){ loc[j] = g_in_cnt[tid*16+j]; sum += loc[j]; }
    ssum[tid] = sum; __syncthreads();
    for (int off=1; off<1024; off<<=1){
        int v = (tid >= off) ? ssum[tid-off] : 0;
        __syncthreads();
        ssum[tid] += v;
        __syncthreads();
    }
    int run = ssum[tid] - sum;
    #pragma unroll
    for (int j=0;j<16;j++){ g_row_ptr[tid*16+j] = run; run += loc[j]; }
    if (tid == 1023) g_row_ptr[NN] = run;
    for (int i=tid; i<NN; i+=1024){
        g_rs_in[i]  = rsqrtf((float)g_in_cnt[i]  + 1.f);
        g_rs_out[i] = rsqrtf((float)g_out_cnt[i] + 1.f);
    }
}

__global__ void scatter_kernel(const int* __restrict__ src, const int* __restrict__ dst){
    int e = blockIdx.x*blockDim.x + threadIdx.x;
    if (e < EE){
        int d = dst[e];
        int p = g_row_ptr[d] + atomicAdd(&g_cursor[d], 1);
        g_csr[p] = src[e];
    }
}

// Pack next_h [K=8192, N=128] into mma-fragment order, tf32-rna.
__global__ void pack_b_kernel(const float* __restrict__ nh){
    size_t idx = (size_t)blockIdx.x*blockDim.x + threadIdx.x;
    if (idx >= PB_F2) return;
    int lane = (int)(idx & 31);
    int ct   = (int)((idx >> 5) & 15);
    int kk4  = (int)((idx >> 9) & 3);
    int kt   = (int)(idx >> 11);
    int k0 = kt*32 + kk4*8 + (lane & 3);
    int n  = ct*8 + (lane >> 2);
    float2 v;
    v.x = rnaf(nh[(size_t)k0*DD + n]);
    v.y = rnaf(nh[(size_t)(k0+4)*DD + n]);
    ((float2*)g_pb)[idx] = v;
}

__global__ void prep_kernel(const float* __restrict__ Wc, const float* __restrict__ bc,
                            const float* __restrict__ Wf, const float* __restrict__ bf,
                            const float* __restrict__ cw, const float* __restrict__ tw){
    int i = blockIdx.x*blockDim.x + threadIdx.x;
    if (i < 2*DD*DD){
        int k = i >> 7, j = i & 127;
        float w = (k < DD) ? Wc[k*DD+j]*cw[j] : Wf[(k-DD)*DD+j]*tw[j];
        g_wcat[i] = __uint_as_float(f2tf(0.5f*w));
        if (i < DD) g_b2[i] = 0.5f*(bc[i]*cw[i] + bf[i]*tw[i]);
    }
}

// combine split-K halves: g_xf = g_xfa + g_xfb
__global__ void reduce_xf(){
    int i = blockIdx.x*blockDim.x + threadIdx.x;
    if (i < NN*DD/4){
        float4 a = ((const float4*)g_xfa)[i];
        float4 b = ((const float4*)g_xfb)[i];
        a.x+=b.x; a.y+=b.y; a.z+=b.z; a.w+=b.w;
        ((float4*)g_xf)[i] = a;
    }
}

// ---------------- SpMM: warp per destination node ----------------
__global__ void spmm_kernel(const float* __restrict__ curr_h){
    int w = (blockIdx.x*blockDim.x + threadIdx.x) >> 5;
    int lane = threadIdx.x & 31;
    if (w >= NN) return;
    const float4* ch4 = (const float4*)curr_h;
    const float4* xf4 = (const float4*)g_xf;
    float sw = g_rs_out[w];
    float4 ac = ch4[w*32 + lane];
    float4 af = xf4[w*32 + lane];
    ac.x*=sw; ac.y*=sw; ac.z*=sw; ac.w*=sw;
    af.x*=sw; af.y*=sw; af.z*=sw; af.w*=sw;
    int s0 = g_row_ptr[w], s1 = g_row_ptr[w+1];
    int base = s0;
    for (; base + 32 <= s1; base += 32){
        int sv = g_csr[base + lane];
        float fv = g_rs_out[sv];
        #pragma unroll 8
        for (int j=0;j<32;j++){
            int   s  = __shfl_sync(0xffffffffu, sv, j);
            float sc = __shfl_sync(0xffffffffu, fv, j);
            float4 vc = ch4[s*32+lane], vf = xf4[s*32+lane];
            ac.x = fmaf(vc.x, sc, ac.x); ac.y = fmaf(vc.y, sc, ac.y);
            ac.z = fmaf(vc.z, sc, ac.z); ac.w = fmaf(vc.w, sc, ac.w);
            af.x = fmaf(vf.x, sc, af.x); af.y = fmaf(vf.y, sc, af.y);
            af.z = fmaf(vf.z, sc, af.z); af.w = fmaf(vf.w, sc, af.w);
        }
    }
    int rem = s1 - base;
    if (rem > 0){
        int   sv = (lane < rem) ? g_csr[base + lane] : 0;
        float fv = g_rs_out[sv];
        for (int j=0;j<rem;j++){
            int   s  = __shfl_sync(0xffffffffu, sv, j);
            float sc = __shfl_sync(0xffffffffu, fv, j);
            float4 vc = ch4[s*32+lane], vf = xf4[s*32+lane];
            ac.x = fmaf(vc.x, sc, ac.x); ac.y = fmaf(vc.y, sc, ac.y);
            ac.z = fmaf(vc.z, sc, ac.z); ac.w = fmaf(vc.w, sc, ac.w);
            af.x = fmaf(vf.x, sc, af.x); af.y = fmaf(vf.y, sc, af.y);
            af.z = fmaf(vf.z, sc, af.z); af.w = fmaf(vf.w, sc, af.w);
        }
    }
    float ri = g_rs_in[w];
    ac.x*=ri; ac.y*=ri; ac.z*=ri; ac.w*=ri;
    af.x*=ri; af.y*=ri; af.z*=ri; af.w*=ri;
    float4* agg4 = (float4*)g_agg;
    agg4[w*64 + lane]      = ac;
    agg4[w*64 + 32 + lane] = af;
}

// ========================================================================
// GEMM1 split-K: partial[khalf][16384,128] = A[:, khalf*4096 + 0:4096] @ nh^T
// BM=128, BK=32, 3-stage ring, 2 CTAs/SM, grid=256 (bid&1 = khalf).
// Single-barrier body, CORRECT ordering:
//   wait_group 1  -> my group m landed
//   __syncthreads -> every thread passed its wait => stage m fully published
//   compute stage m%3
//   prefetch m+2 into stage (m+2)%3 == (m-1)%3 -- safe ONLY here, because
//   the barrier above proves all warps finished body m-1's reads.
// ========================================================================
__global__ void __launch_bounds__(256,2) gemm1_k(const float* __restrict__ A,
                                                 float* __restrict__ Ca,
                                                 float* __restrict__ Cb){
    extern __shared__ float sm[];
    const int tid = threadIdx.x, lane = tid & 31, wid = tid >> 5;
    const int wm = wid & 3, wn = wid >> 2;     // 4x2 warps: 32 rows x 64 cols each
    const int g = lane >> 2, t = lane & 3;
    const int khalf = blockIdx.x & 1;
    const long long brow = (long long)(blockIdx.x >> 1) * 128;
    const long long kof  = (long long)khalf * (MM/2);
    const int kt0 = khalf * NK1;               // packed-B 32-tile base
    float* Cout = khalf ? Cb : Ca;

    float acc[2][8][4];
    #pragma unroll
    for (int i=0;i<2;i++)
        #pragma unroll
        for (int j=0;j<8;j++)
            #pragma unroll
            for (int l=0;l<4;l++) acc[i][j][l] = 0.f;

    auto load_stage = [&](int s, int m){
        if (m < NK1){
            float* as = sm + s*STG1_FLOATS;
            float* bs = as + A1_FLOATS;
            #pragma unroll
            for (int i=0;i<4;i++){                     // A: 128 rows x 32 floats = 1024 x 16B
                int id = tid + i*256;
                int r = id >> 3, c = (id & 7) * 4;
                cp16(as + r*A1_PITCH + c, A + (brow + r)*MM + kof + m*BK1 + c);
            }
            const float* pb = g_pb + (size_t)(kt0 + m)*B1_FLOATS;
            #pragma unroll
            for (int i=0;i<4;i++){                     // B: 1024 x 16B straight copy
                int id = tid + i*256;
                cp16(bs + id*4, pb + id*4);
            }
        }
        asm volatile("cp.async.commit_group;\n" ::: "memory");
    };

    load_stage(0,0); load_stage(1,1);          // pending groups {0,1}

    for (int m=0; m<NK1; m++){
        int s = m % 3;
        asm volatile("cp.async.wait_group 1;\n" ::: "memory");  // group m done (mine)
        __syncthreads();                        // publish: everyone's group m done
        const float* as = sm + s*STG1_FLOATS;
        const float* bs = as + A1_FLOATS;
        #pragma unroll
        for (int kk=0; kk<BK1; kk+=8){
            uint32_t af[2][4];
            #pragma unroll
            for (int mt=0; mt<2; mt++){
                int r0 = wm*32 + mt*16 + g;
                af[mt][0] = f2tf(as[ r0     *A1_PITCH + kk + t    ]);
                af[mt][1] = f2tf(as[(r0 + 8)*A1_PITCH + kk + t    ]);
                af[mt][2] = f2tf(as[ r0     *A1_PITCH + kk + t + 4]);
                af[mt][3] = f2tf(as[(r0 + 8)*A1_PITCH + kk + t + 4]);
            }
            const float* bk = bs + (kk >> 3)*1024 + lane*2;
            #pragma unroll
            for (int nt=0; nt<8; nt++){
                float2 b2 = *(const float2*)(bk + (wn*8 + nt)*64);
                uint32_t b0 = __float_as_uint(b2.x);
                uint32_t b1 = __float_as_uint(b2.y);
                mma8(acc[0][nt], af[0], b0, b1);
                mma8(acc[1][nt], af[1], b0, b1);
            }
        }
        load_stage((m+2)%3, m+2);               // prefetch AFTER barrier+compute
    }

    // epilogue: registers -> gmem only, no smem dependency
    #pragma unroll
    for (int mt=0; mt<2; mt++){
        int r0 = (int)brow + wm*32 + mt*16 + g;
        #pragma unroll
        for (int nt=0; nt<8; nt++){
            int c0 = wn*64 + nt*8 + 2*t;
            float2 v0 = { acc[mt][nt][0], acc[mt][nt][1] };
            float2 v1 = { acc[mt][nt][2], acc[mt][nt][3] };
            *(float2*)(Cout + (size_t) r0   *DD + c0) = v0;
            *(float2*)(Cout + (size_t)(r0+8)*DD + c0) = v1;
        }
    }
}

// ========================================================================
// GEMM2: out = relu(LN(g_agg[16384,256] @ g_wcat[256,128] + b2)*gamma+beta)
// (R14-proven two-sync structure; 15us, not the bottleneck)
// ========================================================================
__global__ void __launch_bounds__(256,1) gemm2_kernel(
    const float* __restrict__ A, const float* __restrict__ B, float* __restrict__ C,
    const float* __restrict__ bias, const float* __restrict__ gamma,
    const float* __restrict__ beta)
{
    extern __shared__ float smem[];
    float* As = smem;
    float* Bs = smem + 2*BM*AST;
    const int tid = threadIdx.x, lane = tid & 31, wid = tid >> 5;
    const int wm = wid & 3, wn = wid >> 2;
    const int g = lane >> 2, t = lane & 3;
    const long long brow = (long long)blockIdx.x * BM;
    const int K = 2*DD;

    float acc[2][8][4];
    #pragma unroll
    for (int i=0;i<2;i++)
        #pragma unroll
        for (int j=0;j<8;j++)
            #pragma unroll
            for (int l=0;l<4;l++) acc[i][j][l] = 0.f;

    const int KT = K / BK;   // 8

    auto load_tile = [&](int buf, int kt){
        const int k0 = kt * BK;
        float* as = As + buf*BM*AST;
        float* bs = Bs + buf*BK*BST;
        #pragma unroll
        for (int i=0;i<4;i++){
            int id = tid + i*256;
            int r = id >> 3, c = (id & 7) * 4;
            cp16(as + r*AST + c, A + (brow + r)*K + k0 + c);
        }
        #pragma unroll
        for (int i=0;i<4;i++){
            int id = tid + i*256;
            int r = id >> 5, c = (id & 31) * 4;
            cp16(bs + r*BST + c, B + (long long)(k0 + r)*BN + c);
        }
        asm volatile("cp.async.commit_group;\n");
    };

    load_tile(0, 0);
    for (int kt=0; kt<KT; kt++){
        int cur = kt & 1;
        if (kt + 1 < KT){
            load_tile(cur^1, kt+1);
            asm volatile("cp.async.wait_group 1;\n");
        } else {
            asm volatile("cp.async.wait_group 0;\n");
        }
        __syncthreads();
        const float* as = As + cur*BM*AST;
        const float* bs = Bs + cur*BK*BST;
        #pragma unroll
        for (int kk=0; kk<BK; kk+=8){
            uint32_t af[2][4];
            #pragma unroll
            for (int mt=0; mt<2; mt++){
                int r0 = wm*32 + mt*16 + g;
                af[mt][0] = f2tf(as[ r0     *AST + kk + t    ]);
                af[mt][1] = f2tf(as[(r0 + 8)*AST + kk + t    ]);
                af[mt][2] = f2tf(as[ r0     *AST + kk + t + 4]);
                af[mt][3] = f2tf(as[(r0 + 8)*AST + kk + t + 4]);
            }
            #pragma unroll
            for (int nt=0; nt<8; nt++){
                int c0 = wn*64 + nt*8 + g;
                uint32_t b0 = __float_as_uint(bs[(kk + t    )*BST + c0]);
                uint32_t b1 = __float_as_uint(bs[(kk + t + 4)*BST + c0]);
                mma8(acc[0][nt], af[0], b0, b1);
                mma8(acc[1][nt], af[1], b0, b1);
            }
        }
        __syncthreads();
    }

    // fused bias + LayerNorm + ReLU via smem staging
    float* sm = smem;
    #pragma unroll
    for (int mt=0; mt<2; mt++){
        int r0 = wm*32 + mt*16 + g;
        #pragma unroll
        for (int nt=0; nt<8; nt++){
            int c0 = wn*64 + nt*8 + 2*t;
            sm[ r0   *EPI_PITCH + c0    ] = acc[mt][nt][0];
            sm[ r0   *EPI_PITCH + c0 + 1] = acc[mt][nt][1];
            sm[(r0+8)*EPI_PITCH + c0    ] = acc[mt][nt][2];
            sm[(r0+8)*EPI_PITCH + c0 + 1] = acc[mt][nt][3];
        }
    }
    __syncthreads();
    if (tid < 128){
        int r = tid;
        float s = 0.f, s2 = 0.f;
        #pragma unroll 8
        for (int c=0;c<128;c++){
            float v = sm[r*EPI_PITCH + c] + bias[c];
            s += v; s2 += v*v;
        }
        float mu   = s  * (1.f/128.f);
        float var  = s2 * (1.f/128.f) - mu*mu;
        float rstd = rsqrtf(var + 1e-5f);
        long long ro = (brow + r) * 128;
        #pragma unroll 8
        for (int c=0;c<128;c++){
            float v = sm[r*EPI_PITCH + c] + bias[c];
            float o = (v - mu)*rstd*gamma[c] + beta[c];
            C[ro + c] = fmaxf(o, 0.f);
        }
    }
}

// ---------------- launcher ----------------
extern "C" void kernel_launch(void* const* d_in, const int* in_sizes, int n_in,
                              void* d_out, int out_size){
    const float* curr_h   = (const float*)d_in[0];
    const float* next_h   = (const float*)d_in[1];
    const float* curr_inc = (const float*)d_in[2];
    const float* Wc    = (const float*)d_in[3];
    const float* bc    = (const float*)d_in[4];
    const float* Wf    = (const float*)d_in[5];
    const float* bf    = (const float*)d_in[6];
    const float* cw    = (const float*)d_in[7];
    const float* tw    = (const float*)d_in[8];
    const float* gamma = (const float*)d_in[9];
    const float* beta  = (const float*)d_in[10];
    const int* esrc = (const int*)d_in[11];
    const int* edst = (const int*)d_in[12];
    float* out = (float*)d_out;

    void *p_xfa, *p_xfb, *p_agg, *p_wcat, *p_b2;
    cudaGetSymbolAddress(&p_xfa,  g_xfa);
    cudaGetSymbolAddress(&p_xfb,  g_xfb);
    cudaGetSymbolAddress(&p_agg,  g_agg);
    cudaGetSymbolAddress(&p_wcat, g_wcat);
    cudaGetSymbolAddress(&p_b2,   g_b2);

    cudaFuncSetAttribute(gemm1_k,      cudaFuncAttributeMaxDynamicSharedMemorySize, GEMM1_SMEM);
    cudaFuncSetAttribute(gemm2_kernel, cudaFuncAttributeMaxDynamicSharedMemorySize, SMEM_BYTES);

    // side stream + events: created once on the (uncaptured) correctness call,
    // reused by capture. Cross-stream events become graph edges.
    static cudaStream_t s2 = nullptr;
    static cudaEvent_t evFork = nullptr, evJoin = nullptr;
    if (!s2){
        cudaStreamCreateWithFlags(&s2, cudaStreamNonBlocking);
        cudaEventCreateWithFlags(&evFork, cudaEventDisableTiming);
        cudaEventCreateWithFlags(&evJoin, cudaEventDisableTiming);
    }

    // fork: CSR/weight prep runs concurrently with the big GEMM
    cudaEventRecord(evFork, 0);
    cudaStreamWaitEvent(s2, evFork, 0);

    // branch (s2): CSR build + weight prep  (~35 us, hidden under gemm1)
    zero_kernel   <<<64,   256, 0, s2>>>();
    degree_kernel <<<2048, 256, 0, s2>>>(esrc, edst);
    scan_kernel   <<<1,   1024, 0, s2>>>();
    scatter_kernel<<<2048, 256, 0, s2>>>(esrc, edst);
    prep_kernel   <<<128,  256, 0, s2>>>(Wc, bc, Wf, bf, cw, tw);
    cudaEventRecord(evJoin, s2);

    // mainline (default stream): pack -> gemm1 -> reduce
    pack_b_kernel <<<1024, 512>>>(next_h);
    gemm1_k       <<<256,  256, GEMM1_SMEM>>>(curr_inc, (float*)p_xfa, (float*)p_xfb);
    reduce_xf     <<<2048, 256>>>();

    // join, then the dependent tail
    cudaStreamWaitEvent(0, evJoin, 0);
    spmm_kernel   <<<2048, 256>>>(curr_h);
    gemm2_kernel  <<<128,  256, SMEM_BYTES>>>((const float*)p_agg, (const float*)p_wcat,
                                              out, (const float*)p_b2, gamma, beta);
}